// round 5
// baseline (speedup 1.0000x reference)
#include <cuda_runtime.h>
#include <cuda_bf16.h>

// ---------------------------------------------------------------------------
// VQC: 4 qubits, 3 layers, BATCH=524288. Single fused persistent kernel.
//  Phase A (per CTA, once): build 16x16 complex layer unitary U in smem
//     (last-layer RZ dropped: pure phase, invisible under |amp|^2).
//  Phase B (grid-stride tiles of 384 elems): 3 elements/thread, packed
//     fma.rn.f32x2 with lanes = adjacent j-columns; one LDS.128 = 4 distinct
//     U scalars shared by 3 elements. Packed-z sign accumulation.
//  TPB=128, launch_bounds(128,5): 5 CTAs/SM -> 20 warps/SM (regfile-tuned).
// ---------------------------------------------------------------------------

#define DIM 16
#define TPB 128
#define EPT 3
#define TILE (TPB * EPT)   // 384
#define MAXGRID 740        // 5 CTAs/SM * 148 SMs

// ---------------- packed f32x2 helpers (PTX-only on Blackwell) -------------
__device__ __forceinline__ unsigned long long pack2(float lo, float hi) {
    unsigned long long r;
    asm("mov.b64 %0, {%1, %2};" : "=l"(r) : "f"(lo), "f"(hi));
    return r;
}
__device__ __forceinline__ void unpack2(unsigned long long v, float& lo, float& hi) {
    asm("mov.b64 {%0, %1}, %2;" : "=f"(lo), "=f"(hi) : "l"(v));
}
__device__ __forceinline__ unsigned long long fma2(unsigned long long a,
                                                   unsigned long long b,
                                                   unsigned long long c) {
    unsigned long long d;
    asm("fma.rn.f32x2 %0, %1, %2, %3;" : "=l"(d) : "l"(a), "l"(b), "l"(c));
    return d;
}
__device__ __forceinline__ unsigned long long mul2(unsigned long long a,
                                                   unsigned long long b) {
    unsigned long long d;
    asm("mul.rn.f32x2 %0, %1, %2;" : "=l"(d) : "l"(a), "l"(b));
    return d;
}

// CNOT ring permutation for one layer (gather index).
__device__ __forceinline__ int cnot_q(int idx) {
    int q = idx;
#pragma unroll
    for (int i = 3; i >= 0; --i)
        q = q ^ ((((q >> (3 - i)) & 1)) << (3 - ((i + 1) & 3)));
    return q;
}

__global__ __launch_bounds__(TPB, 5)
void vqc_fused_kernel(const float* __restrict__ x, const float* __restrict__ w,
                      float* __restrict__ out, int B, int numTiles) {
    __shared__ float2 sState[DIM * 17];
    __shared__ float4 sGate[12];
    // sU[k][c]: c=0..3 -> re[k][4c..4c+3], c=4..7 -> im[k][4(c-4)..]
    __shared__ ulonglong2 sU[DIM][8];

    const int t = threadIdx.x;

    // ---------------- Phase A: build U cooperatively (128 threads) ---------
    if (t < 12) {
        float cy, sy, cz, sz;
        __sincosf(0.5f * w[t * 2 + 0], &sy, &cy);
        __sincosf(0.5f * w[t * 2 + 1], &sz, &cz);
        sGate[t] = make_float4(cy, sy, cz, sz);
    }
#pragma unroll
    for (int e = t; e < 256; e += TPB) {
        const int col = e >> 4, amp = e & 15;
        sState[col * 17 + amp] = make_float2((amp == col) ? 1.0f : 0.0f, 0.0f);
    }
    __syncthreads();

#pragma unroll
    for (int layer = 0; layer < 3; ++layer) {
        {   // CNOT ring stage: read-all then write-all
            float2 v0, v1;
            {
                const int col = t >> 4, idx = t & 15;
                v0 = sState[col * 17 + cnot_q(idx)];
            }
            {
                const int e = t + 128;
                const int col = e >> 4, idx = e & 15;
                v1 = sState[col * 17 + cnot_q(idx)];
            }
            __syncthreads();
            {
                const int col = t >> 4, idx = t & 15;
                sState[col * 17 + idx] = v0;
            }
            {
                const int e = t + 128;
                const int col = e >> 4, idx = e & 15;
                sState[col * 17 + idx] = v1;
            }
            __syncthreads();
        }
#pragma unroll
        for (int g = 0; g < 4; ++g) {
            const int bit = 3 - g, mask = 1 << bit;
            const int col = t >> 3, pair = t & 7;
            const int i0 = ((pair >> bit) << (bit + 1)) | (pair & (mask - 1));
            const int i1 = i0 | mask;
            const float4 gp = sGate[layer * 4 + g];
            const float cy = gp.x, sy = gp.y;
            const float2 a0 = sState[col * 17 + i0];
            const float2 a1 = sState[col * 17 + i1];
            float b0r = cy * a0.x - sy * a1.x, b0i = cy * a0.y - sy * a1.y;
            float b1r = sy * a0.x + cy * a1.x, b1i = sy * a0.y + cy * a1.y;
            if (layer != 2) {   // RZ (dropped on last layer: pure phase)
                const float cz = gp.z, sz = gp.w;
                const float o0r = cz * b0r + sz * b0i, o0i = cz * b0i - sz * b0r;
                const float o1r = cz * b1r - sz * b1i, o1i = cz * b1i + sz * b1r;
                b0r = o0r; b0i = o0i; b1r = o1r; b1i = o1i;
            }
            sState[col * 17 + i0] = make_float2(b0r, b0i);
            sState[col * 17 + i1] = make_float2(b1r, b1i);
            __syncthreads();
        }
    }
#pragma unroll
    for (int e = t; e < 256; e += TPB) {   // layout: row k = [re x16 | im x16]
        const int k = e >> 4, j = e & 15;
        const float2 f = sState[j * 17 + k];
        float* fU = reinterpret_cast<float*>(sU);
        fU[k * 32 + j]      = f.x;
        fU[k * 32 + 16 + j] = f.y;
    }
    __syncthreads();

    // sign vectors for packed-z accumulation (built once)
    const unsigned long long SPP = pack2( 1.f,  1.f);
    const unsigned long long SPM = pack2( 1.f, -1.f);
    const unsigned long long SMP = pack2(-1.f,  1.f);
    const unsigned long long SMM = pack2(-1.f, -1.f);

    // ---------------- Phase B: persistent grid-stride tiles ----------------
    for (int tile = blockIdx.x; tile < numTiles; tile += gridDim.x) {
        const int base = tile * TILE + t;

        bool valid[EPT];
        unsigned long long pp[EPT][8];   // (p_2j, p_2j+1)
#pragma unroll
        for (int e = 0; e < EPT; ++e) {
            const int b = base + e * TPB;
            valid[e] = (b < B);
            const float4 xv = valid[e] ? reinterpret_cast<const float4*>(x)[b]
                                       : make_float4(0.f, 0.f, 0.f, 0.f);
            float c0, s0, c1, s1, c2, s2, c3, s3;
            __sincosf(0.5f * xv.x, &s0, &c0);
            __sincosf(0.5f * xv.y, &s1, &c1);
            __sincosf(0.5f * xv.z, &s2, &c2);
            __sincosf(0.5f * xv.w, &s3, &c3);
            const float m[4] = {c0 * c1, c0 * s1, s0 * c1, s0 * s1};
            const unsigned long long n01 = pack2(c2 * c3, c2 * s3);
            const unsigned long long n23 = pack2(s2 * c3, s2 * s3);
#pragma unroll
            for (int a = 0; a < 4; ++a) {
                const unsigned long long md = pack2(m[a], m[a]);
                pp[e][a * 2 + 0] = mul2(md, n01);
                pp[e][a * 2 + 1] = mul2(md, n23);
            }
        }

        unsigned long long z01[EPT], z23[EPT];
#pragma unroll
        for (int e = 0; e < EPT; ++e) { z01[e] = 0ull; z23[e] = 0ull; }

#pragma unroll
        for (int k = 0; k < DIM; ++k) {
            const ulonglong2 r0 = sU[k][0], r1 = sU[k][1];
            const ulonglong2 r2 = sU[k][2], r3 = sU[k][3];
            unsigned long long aR[EPT];
#pragma unroll
            for (int e = 0; e < EPT; ++e) {
                unsigned long long a = mul2(r0.x, pp[e][0]);
                a = fma2(r0.y, pp[e][1], a);
                a = fma2(r1.x, pp[e][2], a);
                a = fma2(r1.y, pp[e][3], a);
                a = fma2(r2.x, pp[e][4], a);
                a = fma2(r2.y, pp[e][5], a);
                a = fma2(r3.x, pp[e][6], a);
                a = fma2(r3.y, pp[e][7], a);
                aR[e] = a;
            }
            const ulonglong2 i0 = sU[k][4], i1 = sU[k][5];
            const ulonglong2 i2 = sU[k][6], i3 = sU[k][7];
            // compile-time sign vectors for this k
            const unsigned long long s01 =
                (k & 8) ? ((k & 4) ? SMM : SMP) : ((k & 4) ? SPM : SPP);
            const unsigned long long s23 =
                (k & 2) ? ((k & 1) ? SMM : SMP) : ((k & 1) ? SPM : SPP);
#pragma unroll
            for (int e = 0; e < EPT; ++e) {
                unsigned long long a = mul2(i0.x, pp[e][0]);
                a = fma2(i0.y, pp[e][1], a);
                a = fma2(i1.x, pp[e][2], a);
                a = fma2(i1.y, pp[e][3], a);
                a = fma2(i2.x, pp[e][4], a);
                a = fma2(i2.y, pp[e][5], a);
                a = fma2(i3.x, pp[e][6], a);
                a = fma2(i3.y, pp[e][7], a);
                float rl, rh, il, ih;
                unpack2(aR[e], rl, rh);
                unpack2(a, il, ih);
                const float re = rl + rh, im = il + ih;
                const float pr = fmaf(im, im, re * re);
                const unsigned long long prp = pack2(pr, pr);
                z01[e] = fma2(s01, prp, z01[e]);
                z23[e] = fma2(s23, prp, z23[e]);
            }
        }

#pragma unroll
        for (int e = 0; e < EPT; ++e) {
            if (!valid[e]) continue;
            float z0, z1, z2, z3;
            unpack2(z01[e], z0, z1);
            unpack2(z23[e], z2, z3);
            reinterpret_cast<float4*>(out)[base + e * TPB] =
                make_float4(z0, z1, z2, z3);
        }
    }
}

// ---------------------------------------------------------------------------
extern "C" void kernel_launch(void* const* d_in, const int* in_sizes, int n_in,
                              void* d_out, int out_size) {
    int ix = 0, iw = 1;
    if (n_in >= 2 && in_sizes[0] <= in_sizes[1]) { ix = 1; iw = 0; }
    const float* x = (const float*)d_in[ix];
    const float* w = (const float*)d_in[iw];
    float* out = (float*)d_out;
    const int B = in_sizes[ix] / 4;

    const int numTiles = (B + TILE - 1) / TILE;
    const int grid = numTiles < MAXGRID ? numTiles : MAXGRID;
    vqc_fused_kernel<<<grid, TPB>>>(x, w, out, B, numTiles);
}

// round 6
// speedup vs baseline: 2.4547x; 2.4547x over previous
#include <cuda_runtime.h>
#include <cuda_bf16.h>

// ---------------------------------------------------------------------------
// VQC: 4 qubits, 3 layers, BATCH=524288. Single fused kernel.
//  Phase A (per CTA): build 16x16 complex layer unitary U in smem
//     (last-layer RZ dropped: pure phase, invisible under |amp|^2).
//  Phase B: EPT=2 elements/thread, packed fma.rn.f32x2 with lanes =
//     adjacent j-columns (one LDS.128 = 4 distinct U scalars, shared by both
//     elements). 512 real FMA/elem = flop floor of the 32x16 matvec.
//  TPB=256, launch_bounds(256,3): ~80 live regs -> 24 warps/SM, no spill.
// ---------------------------------------------------------------------------

#define DIM 16
#define TPB 256
#define EPT 2
#define TILE (TPB * EPT)   // 512

// ---------------- packed f32x2 helpers (PTX-only on Blackwell) -------------
__device__ __forceinline__ unsigned long long pack2(float lo, float hi) {
    unsigned long long r;
    asm("mov.b64 %0, {%1, %2};" : "=l"(r) : "f"(lo), "f"(hi));
    return r;
}
__device__ __forceinline__ void unpack2(unsigned long long v, float& lo, float& hi) {
    asm("mov.b64 {%0, %1}, %2;" : "=f"(lo), "=f"(hi) : "l"(v));
}
__device__ __forceinline__ unsigned long long fma2(unsigned long long a,
                                                   unsigned long long b,
                                                   unsigned long long c) {
    unsigned long long d;
    asm("fma.rn.f32x2 %0, %1, %2, %3;" : "=l"(d) : "l"(a), "l"(b), "l"(c));
    return d;
}
__device__ __forceinline__ unsigned long long mul2(unsigned long long a,
                                                   unsigned long long b) {
    unsigned long long d;
    asm("mul.rn.f32x2 %0, %1, %2;" : "=l"(d) : "l"(a), "l"(b));
    return d;
}

// CNOT ring permutation for one layer (gather index).
__device__ __forceinline__ int cnot_q(int idx) {
    int q = idx;
#pragma unroll
    for (int i = 3; i >= 0; --i)
        q = q ^ ((((q >> (3 - i)) & 1)) << (3 - ((i + 1) & 3)));
    return q;
}

__global__ __launch_bounds__(TPB, 3)
void vqc_fused_kernel(const float* __restrict__ x, const float* __restrict__ w,
                      float* __restrict__ out, int B) {
    __shared__ float2 sState[DIM * 17];
    __shared__ float4 sGate[12];
    // sU[k][c]: c=0..3 -> re[k][4c..4c+3], c=4..7 -> im[k][4(c-4)..]
    __shared__ ulonglong2 sU[DIM][8];

    const int t = threadIdx.x;

    // ---------------- Phase A: build U cooperatively (R3-verified) ---------
    if (t < 12) {
        float cy, sy, cz, sz;
        __sincosf(0.5f * w[t * 2 + 0], &sy, &cy);
        __sincosf(0.5f * w[t * 2 + 1], &sz, &cz);
        sGate[t] = make_float4(cy, sy, cz, sz);
    }
    {
        const int col = t >> 4, amp = t & 15;
        sState[col * 17 + amp] = make_float2((amp == col) ? 1.0f : 0.0f, 0.0f);
    }
    __syncthreads();

#pragma unroll
    for (int layer = 0; layer < 3; ++layer) {
        {   // CNOT ring stage
            const int col = t >> 4, idx = t & 15;
            const float2 v = sState[col * 17 + cnot_q(idx)];
            __syncthreads();
            sState[col * 17 + idx] = v;
            __syncthreads();
        }
#pragma unroll
        for (int g = 0; g < 4; ++g) {
            if (t < 128) {
                const int bit = 3 - g, mask = 1 << bit;
                const int col = t >> 3, pair = t & 7;
                const int i0 = ((pair >> bit) << (bit + 1)) | (pair & (mask - 1));
                const int i1 = i0 | mask;
                const float4 gp = sGate[layer * 4 + g];
                const float cy = gp.x, sy = gp.y;
                const float2 a0 = sState[col * 17 + i0];
                const float2 a1 = sState[col * 17 + i1];
                float b0r = cy * a0.x - sy * a1.x, b0i = cy * a0.y - sy * a1.y;
                float b1r = sy * a0.x + cy * a1.x, b1i = sy * a0.y + cy * a1.y;
                if (layer != 2) {   // RZ (dropped on last layer: pure phase)
                    const float cz = gp.z, sz = gp.w;
                    const float o0r = cz * b0r + sz * b0i, o0i = cz * b0i - sz * b0r;
                    const float o1r = cz * b1r - sz * b1i, o1i = cz * b1i + sz * b1r;
                    b0r = o0r; b0i = o0i; b1r = o1r; b1i = o1i;
                }
                sState[col * 17 + i0] = make_float2(b0r, b0i);
                sState[col * 17 + i1] = make_float2(b1r, b1i);
            }
            __syncthreads();
        }
    }
    {   // layout: row k = [re x16 | im x16] floats
        const int k = t >> 4, j = t & 15;
        const float2 f = sState[j * 17 + k];
        float* fU = reinterpret_cast<float*>(sU);
        fU[k * 32 + j]      = f.x;
        fU[k * 32 + 16 + j] = f.y;
    }
    __syncthreads();

    // ---------------- Phase B: 2 elements per thread -----------------------
    const int base = blockIdx.x * TILE + t;

    bool valid[EPT];
    unsigned long long pp[EPT][8];   // (p_2j, p_2j+1)
#pragma unroll
    for (int e = 0; e < EPT; ++e) {
        const int b = base + e * TPB;
        valid[e] = (b < B);
        const float4 xv = valid[e] ? reinterpret_cast<const float4*>(x)[b]
                                   : make_float4(0.f, 0.f, 0.f, 0.f);
        float c0, s0, c1, s1, c2, s2, c3, s3;
        __sincosf(0.5f * xv.x, &s0, &c0);
        __sincosf(0.5f * xv.y, &s1, &c1);
        __sincosf(0.5f * xv.z, &s2, &c2);
        __sincosf(0.5f * xv.w, &s3, &c3);
        const float m[4] = {c0 * c1, c0 * s1, s0 * c1, s0 * s1};
        const unsigned long long n01 = pack2(c2 * c3, c2 * s3);
        const unsigned long long n23 = pack2(s2 * c3, s2 * s3);
#pragma unroll
        for (int a = 0; a < 4; ++a) {
            const unsigned long long md = pack2(m[a], m[a]);
            pp[e][a * 2 + 0] = mul2(md, n01);
            pp[e][a * 2 + 1] = mul2(md, n23);
        }
    }

    float z0[EPT], z1[EPT], z2[EPT], z3[EPT];
#pragma unroll
    for (int e = 0; e < EPT; ++e) { z0[e] = 0.f; z1[e] = 0.f; z2[e] = 0.f; z3[e] = 0.f; }

#pragma unroll
    for (int k = 0; k < DIM; ++k) {
        const ulonglong2 r0 = sU[k][0], r1 = sU[k][1];
        const ulonglong2 r2 = sU[k][2], r3 = sU[k][3];
        unsigned long long aR[EPT];
#pragma unroll
        for (int e = 0; e < EPT; ++e) {
            unsigned long long a = mul2(r0.x, pp[e][0]);
            a = fma2(r0.y, pp[e][1], a);
            a = fma2(r1.x, pp[e][2], a);
            a = fma2(r1.y, pp[e][3], a);
            a = fma2(r2.x, pp[e][4], a);
            a = fma2(r2.y, pp[e][5], a);
            a = fma2(r3.x, pp[e][6], a);
            a = fma2(r3.y, pp[e][7], a);
            aR[e] = a;
        }
        const ulonglong2 i0 = sU[k][4], i1 = sU[k][5];
        const ulonglong2 i2 = sU[k][6], i3 = sU[k][7];
#pragma unroll
        for (int e = 0; e < EPT; ++e) {
            unsigned long long a = mul2(i0.x, pp[e][0]);
            a = fma2(i0.y, pp[e][1], a);
            a = fma2(i1.x, pp[e][2], a);
            a = fma2(i1.y, pp[e][3], a);
            a = fma2(i2.x, pp[e][4], a);
            a = fma2(i2.y, pp[e][5], a);
            a = fma2(i3.x, pp[e][6], a);
            a = fma2(i3.y, pp[e][7], a);
            float rl, rh, il, ih;
            unpack2(aR[e], rl, rh);   // register-pair aliases: free
            unpack2(a, il, ih);
            const float re = rl + rh, im = il + ih;
            const float pr = fmaf(im, im, re * re);
            if (k & 8) z0[e] -= pr; else z0[e] += pr;
            if (k & 4) z1[e] -= pr; else z1[e] += pr;
            if (k & 2) z2[e] -= pr; else z2[e] += pr;
            if (k & 1) z3[e] -= pr; else z3[e] += pr;
        }
    }

#pragma unroll
    for (int e = 0; e < EPT; ++e) {
        if (!valid[e]) continue;
        reinterpret_cast<float4*>(out)[base + e * TPB] =
            make_float4(z0[e], z1[e], z2[e], z3[e]);
    }
}

// ---------------------------------------------------------------------------
extern "C" void kernel_launch(void* const* d_in, const int* in_sizes, int n_in,
                              void* d_out, int out_size) {
    int ix = 0, iw = 1;
    if (n_in >= 2 && in_sizes[0] <= in_sizes[1]) { ix = 1; iw = 0; }
    const float* x = (const float*)d_in[ix];
    const float* w = (const float*)d_in[iw];
    float* out = (float*)d_out;
    const int B = in_sizes[ix] / 4;

    const int grid = (B + TILE - 1) / TILE;
    vqc_fused_kernel<<<grid, TPB>>>(x, w, out, B);
}

// round 7
// speedup vs baseline: 2.7282x; 1.1115x over previous
#include <cuda_runtime.h>
#include <cuda_bf16.h>

// ---------------------------------------------------------------------------
// VQC: 4 qubits, 3 layers, BATCH=524288. Single fused kernel.
//  z_w(x) is an exact 81-term polynomial in {1, cos x_q, sin x_q}^{⊗4}:
//    z_w = p^T M_w p,  M_w = Re(U^† S_w U)  (U = batch-invariant layer unitary)
//    p_j p_j' factorizes per qubit into {c²,cs,s²} = affine in (1,cos,sin).
//  Phase A: build U (verified builder; last-layer RZ dropped — cancels in M).
//  Phase M: M_w[j,j'] = Σ_k s_wk (Ur Ur' + Ui Ui')      (256 threads, 1 pair each)
//  Phase T: T_w[m] = (1/16) Σ_b ± M_w[b, b^M2]          (81 threads)
//  Phase B: per elem: v-monomials via packed fma.rn.f32x2, lanes = (w0,w1)/(w2,w3).
//    Cost/elem: 8 MUFU + 64 mul2 + 162 fma2  (vs 426 fma-ops in the matvec form).
// ---------------------------------------------------------------------------

#define DIM 16
#define TPB 256
#define EPT 2
#define TILE (TPB * EPT)   // 512

// ---------------- packed f32x2 helpers (PTX-only on Blackwell) -------------
__device__ __forceinline__ unsigned long long pack2(float lo, float hi) {
    unsigned long long r;
    asm("mov.b64 %0, {%1, %2};" : "=l"(r) : "f"(lo), "f"(hi));
    return r;
}
__device__ __forceinline__ void unpack2(unsigned long long v, float& lo, float& hi) {
    asm("mov.b64 {%0, %1}, %2;" : "=f"(lo), "=f"(hi) : "l"(v));
}
__device__ __forceinline__ unsigned long long fma2(unsigned long long a,
                                                   unsigned long long b,
                                                   unsigned long long c) {
    unsigned long long d;
    asm("fma.rn.f32x2 %0, %1, %2, %3;" : "=l"(d) : "l"(a), "l"(b), "l"(c));
    return d;
}
__device__ __forceinline__ unsigned long long mul2(unsigned long long a,
                                                   unsigned long long b) {
    unsigned long long d;
    asm("mul.rn.f32x2 %0, %1, %2;" : "=l"(d) : "l"(a), "l"(b));
    return d;
}

// CNOT ring permutation for one layer (gather index).
__device__ __forceinline__ int cnot_q(int idx) {
    int q = idx;
#pragma unroll
    for (int i = 3; i >= 0; --i)
        q = q ^ ((((q >> (3 - i)) & 1)) << (3 - ((i + 1) & 3)));
    return q;
}

__global__ __launch_bounds__(TPB, 2)
void vqc_poly_kernel(const float* __restrict__ x, const float* __restrict__ w,
                     float* __restrict__ out, int B) {
    __shared__ float2 sState[DIM * 17];
    __shared__ float4 sGate[12];
    __shared__ float4 sM[256];   // M_w[j*16+j'] as w-vector
    __shared__ float4 sT[81];    // T_w[m] as w-vector

    const int t = threadIdx.x;

    // ---------------- Phase A: build U (R6-verified builder) ---------------
    if (t < 12) {
        float cy, sy, cz, sz;
        __sincosf(0.5f * w[t * 2 + 0], &sy, &cy);
        __sincosf(0.5f * w[t * 2 + 1], &sz, &cz);
        sGate[t] = make_float4(cy, sy, cz, sz);
    }
    {
        const int col = t >> 4, amp = t & 15;
        sState[col * 17 + amp] = make_float2((amp == col) ? 1.0f : 0.0f, 0.0f);
    }
    __syncthreads();

#pragma unroll
    for (int layer = 0; layer < 3; ++layer) {
        {   // CNOT ring stage
            const int col = t >> 4, idx = t & 15;
            const float2 v = sState[col * 17 + cnot_q(idx)];
            __syncthreads();
            sState[col * 17 + idx] = v;
            __syncthreads();
        }
#pragma unroll
        for (int g = 0; g < 4; ++g) {
            if (t < 128) {
                const int bit = 3 - g, mask = 1 << bit;
                const int col = t >> 3, pair = t & 7;
                const int i0 = ((pair >> bit) << (bit + 1)) | (pair & (mask - 1));
                const int i1 = i0 | mask;
                const float4 gp = sGate[layer * 4 + g];
                const float cy = gp.x, sy = gp.y;
                const float2 a0 = sState[col * 17 + i0];
                const float2 a1 = sState[col * 17 + i1];
                float b0r = cy * a0.x - sy * a1.x, b0i = cy * a0.y - sy * a1.y;
                float b1r = sy * a0.x + cy * a1.x, b1i = sy * a0.y + cy * a1.y;
                if (layer != 2) {   // RZ (dropped on last layer: cancels in U^H S U)
                    const float cz = gp.z, sz = gp.w;
                    const float o0r = cz * b0r + sz * b0i, o0i = cz * b0i - sz * b0r;
                    const float o1r = cz * b1r - sz * b1i, o1i = cz * b1i + sz * b1r;
                    b0r = o0r; b0i = o0i; b1r = o1r; b1i = o1i;
                }
                sState[col * 17 + i0] = make_float2(b0r, b0i);
                sState[col * 17 + i1] = make_float2(b1r, b1i);
            }
            __syncthreads();
        }
    }

    // ---------------- Phase M: M_w[j,j'] (one (j,j') pair per thread) ------
    {
        const int j = t >> 4, jp = t & 15;
        float m0 = 0.f, m1 = 0.f, m2 = 0.f, m3 = 0.f;
#pragma unroll
        for (int k = 0; k < DIM; ++k) {
            // U[k][col] = sState[col*17 + k]
            const float2 a = sState[j * 17 + k];
            const float2 b = sState[jp * 17 + k];
            const float pr = a.x * b.x + a.y * b.y;
            if (k & 8) m0 -= pr; else m0 += pr;
            if (k & 4) m1 -= pr; else m1 += pr;
            if (k & 2) m2 -= pr; else m2 += pr;
            if (k & 1) m3 -= pr; else m3 += pr;
        }
        sM[j * 16 + jp] = make_float4(m0, m1, m2, m3);
    }
    __syncthreads();

    // ---------------- Phase T: 81 monomial coefficients --------------------
    if (t < 81) {
        const int i0 = t / 27, i1 = (t / 9) % 3, i2 = (t / 3) % 3, i3 = t % 3;
        const int M1 = ((i0 == 1) << 3) | ((i1 == 1) << 2) | ((i2 == 1) << 1) | (i3 == 1);
        const int M2 = ((i0 == 2) << 3) | ((i1 == 2) << 2) | ((i2 == 2) << 1) | (i3 == 2);
        float a0 = 0.f, a1 = 0.f, a2 = 0.f, a3 = 0.f;
#pragma unroll
        for (int b = 0; b < 16; ++b) {
            const float4 mm = sM[b * 16 + (b ^ M2)];
            const float sg = (__popc(b & M1) & 1) ? -1.f : 1.f;
            a0 += sg * mm.x; a1 += sg * mm.y; a2 += sg * mm.z; a3 += sg * mm.w;
        }
        const float s = 0.0625f;
        sT[t] = make_float4(a0 * s, a1 * s, a2 * s, a3 * s);
    }
    __syncthreads();

    // ---------------- Phase B: 81-term polynomial per element --------------
    const int base = blockIdx.x * TILE + t;

    bool valid[EPT];
    // duplicated monomial bases: g over (q0,q1), h over (q2,q3); index i*3+i'
    unsigned long long g[EPT][9], h[EPT][9];
#pragma unroll
    for (int e = 0; e < EPT; ++e) {
        const int b = base + e * TPB;
        valid[e] = (b < B);
        const float4 xv = valid[e] ? reinterpret_cast<const float4*>(x)[b]
                                   : make_float4(0.f, 0.f, 0.f, 0.f);
        float c0, s0, c1, s1, c2, s2, c3, s3;
        __sincosf(xv.x, &s0, &c0);   // full angle (double-angle absorbed into T)
        __sincosf(xv.y, &s1, &c1);
        __sincosf(xv.z, &s2, &c2);
        __sincosf(xv.w, &s3, &c3);
        g[e][1] = pack2(c1, c1);
        g[e][2] = pack2(s1, s1);
        g[e][3] = pack2(c0, c0);
        g[e][6] = pack2(s0, s0);
        g[e][4] = mul2(g[e][3], g[e][1]);
        g[e][5] = mul2(g[e][3], g[e][2]);
        g[e][7] = mul2(g[e][6], g[e][1]);
        g[e][8] = mul2(g[e][6], g[e][2]);
        h[e][1] = pack2(c3, c3);
        h[e][2] = pack2(s3, s3);
        h[e][3] = pack2(c2, c2);
        h[e][6] = pack2(s2, s2);
        h[e][4] = mul2(h[e][3], h[e][1]);
        h[e][5] = mul2(h[e][3], h[e][2]);
        h[e][7] = mul2(h[e][6], h[e][1]);
        h[e][8] = mul2(h[e][6], h[e][2]);
    }

    // init with monomial m=0 (value 1): z = T[0]
    unsigned long long z01[EPT], z23[EPT];
    {
        const float4 c = sT[0];
#pragma unroll
        for (int e = 0; e < EPT; ++e) {
            z01[e] = pack2(c.x, c.y);
            z23[e] = pack2(c.z, c.w);
        }
    }

#pragma unroll
    for (int gi = 0; gi < 9; ++gi) {
#pragma unroll
        for (int hi = 0; hi < 9; ++hi) {
            if (gi == 0 && hi == 0) continue;
            const int m = gi * 9 + hi;
            const float4 c = sT[m];                      // one LDS.128 per monomial
            const unsigned long long cp01 = pack2(c.x, c.y);
            const unsigned long long cp23 = pack2(c.z, c.w);
#pragma unroll
            for (int e = 0; e < EPT; ++e) {
                const unsigned long long q =
                    (gi == 0) ? h[e][hi]
                              : ((hi == 0) ? g[e][gi] : mul2(g[e][gi], h[e][hi]));
                z01[e] = fma2(cp01, q, z01[e]);
                z23[e] = fma2(cp23, q, z23[e]);
            }
        }
    }

#pragma unroll
    for (int e = 0; e < EPT; ++e) {
        if (!valid[e]) continue;
        float z0, z1, z2, z3;
        unpack2(z01[e], z0, z1);
        unpack2(z23[e], z2, z3);
        reinterpret_cast<float4*>(out)[base + e * TPB] = make_float4(z0, z1, z2, z3);
    }
}

// ---------------------------------------------------------------------------
extern "C" void kernel_launch(void* const* d_in, const int* in_sizes, int n_in,
                              void* d_out, int out_size) {
    int ix = 0, iw = 1;
    if (n_in >= 2 && in_sizes[0] <= in_sizes[1]) { ix = 1; iw = 0; }
    const float* x = (const float*)d_in[ix];
    const float* w = (const float*)d_in[iw];
    float* out = (float*)d_out;
    const int B = in_sizes[ix] / 4;

    const int grid = (B + TILE - 1) / TILE;
    vqc_poly_kernel<<<grid, TPB>>>(x, w, out, B);
}

// round 8
// speedup vs baseline: 3.1517x; 1.1552x over previous
#include <cuda_runtime.h>
#include <cuda_bf16.h>

// ---------------------------------------------------------------------------
// VQC: 4 qubits, 3 layers, BATCH=524288.
// z_w(x) is an exact 81-term polynomial in {1, cos x_q, sin x_q}^{⊗4}
// (coefficients T depend only on weights):
//   z_w = p^T M_w p,  M_w = Re(U^† S_w U),  monomial transform in closed form.
// Kernel 1 (1 block): build U -> M -> T  (verified R7 phases), write g_T[81].
// Kernel 2 (EPT=1, TPB=128, 8 CTAs/SM): per element, Horner-factored
//   z = Σ_gi g_gi (Σ_hi T[gi,hi] h_hi), packed fma.rn.f32x2 lanes=(w0,w1)/(w2,w3).
// ---------------------------------------------------------------------------

#define DIM 16

__device__ float4 g_T[81];

// ---------------- packed f32x2 helpers (PTX-only on Blackwell) -------------
__device__ __forceinline__ unsigned long long pack2(float lo, float hi) {
    unsigned long long r;
    asm("mov.b64 %0, {%1, %2};" : "=l"(r) : "f"(lo), "f"(hi));
    return r;
}
__device__ __forceinline__ void unpack2(unsigned long long v, float& lo, float& hi) {
    asm("mov.b64 {%0, %1}, %2;" : "=f"(lo), "=f"(hi) : "l"(v));
}
__device__ __forceinline__ unsigned long long fma2(unsigned long long a,
                                                   unsigned long long b,
                                                   unsigned long long c) {
    unsigned long long d;
    asm("fma.rn.f32x2 %0, %1, %2, %3;" : "=l"(d) : "l"(a), "l"(b), "l"(c));
    return d;
}
__device__ __forceinline__ unsigned long long mul2(unsigned long long a,
                                                   unsigned long long b) {
    unsigned long long d;
    asm("mul.rn.f32x2 %0, %1, %2;" : "=l"(d) : "l"(a), "l"(b));
    return d;
}

// CNOT ring permutation for one layer (gather index).
__device__ __forceinline__ int cnot_q(int idx) {
    int q = idx;
#pragma unroll
    for (int i = 3; i >= 0; --i)
        q = q ^ ((((q >> (3 - i)) & 1)) << (3 - ((i + 1) & 3)));
    return q;
}

// ---------------- Kernel 1: weights -> polynomial coefficients T -----------
__global__ void vqc_build_T(const float* __restrict__ w) {
    __shared__ float2 sState[DIM * 17];
    __shared__ float4 sGate[12];
    __shared__ float4 sM[256];

    const int t = threadIdx.x;

    // Phase A: build U (verified builder; last-layer RZ cancels in U^H S U)
    if (t < 12) {
        float cy, sy, cz, sz;
        __sincosf(0.5f * w[t * 2 + 0], &sy, &cy);
        __sincosf(0.5f * w[t * 2 + 1], &sz, &cz);
        sGate[t] = make_float4(cy, sy, cz, sz);
    }
    {
        const int col = t >> 4, amp = t & 15;
        sState[col * 17 + amp] = make_float2((amp == col) ? 1.0f : 0.0f, 0.0f);
    }
    __syncthreads();

#pragma unroll
    for (int layer = 0; layer < 3; ++layer) {
        {   // CNOT ring stage
            const int col = t >> 4, idx = t & 15;
            const float2 v = sState[col * 17 + cnot_q(idx)];
            __syncthreads();
            sState[col * 17 + idx] = v;
            __syncthreads();
        }
#pragma unroll
        for (int g = 0; g < 4; ++g) {
            if (t < 128) {
                const int bit = 3 - g, mask = 1 << bit;
                const int col = t >> 3, pair = t & 7;
                const int i0 = ((pair >> bit) << (bit + 1)) | (pair & (mask - 1));
                const int i1 = i0 | mask;
                const float4 gp = sGate[layer * 4 + g];
                const float cy = gp.x, sy = gp.y;
                const float2 a0 = sState[col * 17 + i0];
                const float2 a1 = sState[col * 17 + i1];
                float b0r = cy * a0.x - sy * a1.x, b0i = cy * a0.y - sy * a1.y;
                float b1r = sy * a0.x + cy * a1.x, b1i = sy * a0.y + cy * a1.y;
                if (layer != 2) {
                    const float cz = gp.z, sz = gp.w;
                    const float o0r = cz * b0r + sz * b0i, o0i = cz * b0i - sz * b0r;
                    const float o1r = cz * b1r - sz * b1i, o1i = cz * b1i + sz * b1r;
                    b0r = o0r; b0i = o0i; b1r = o1r; b1i = o1i;
                }
                sState[col * 17 + i0] = make_float2(b0r, b0i);
                sState[col * 17 + i1] = make_float2(b1r, b1i);
            }
            __syncthreads();
        }
    }

    // Phase M: M_w[j,j'] = sum_k s_wk (Ur Ur' + Ui Ui')
    {
        const int j = t >> 4, jp = t & 15;
        float m0 = 0.f, m1 = 0.f, m2 = 0.f, m3 = 0.f;
#pragma unroll
        for (int k = 0; k < DIM; ++k) {
            const float2 a = sState[j * 17 + k];
            const float2 b = sState[jp * 17 + k];
            const float pr = a.x * b.x + a.y * b.y;
            if (k & 8) m0 -= pr; else m0 += pr;
            if (k & 4) m1 -= pr; else m1 += pr;
            if (k & 2) m2 -= pr; else m2 += pr;
            if (k & 1) m3 -= pr; else m3 += pr;
        }
        sM[j * 16 + jp] = make_float4(m0, m1, m2, m3);
    }
    __syncthreads();

    // Phase T: 81 monomial coefficients -> global
    if (t < 81) {
        const int i0 = t / 27, i1 = (t / 9) % 3, i2 = (t / 3) % 3, i3 = t % 3;
        const int M1 = ((i0 == 1) << 3) | ((i1 == 1) << 2) | ((i2 == 1) << 1) | (i3 == 1);
        const int M2 = ((i0 == 2) << 3) | ((i1 == 2) << 2) | ((i2 == 2) << 1) | (i3 == 2);
        float a0 = 0.f, a1 = 0.f, a2 = 0.f, a3 = 0.f;
#pragma unroll
        for (int b = 0; b < 16; ++b) {
            const float4 mm = sM[b * 16 + (b ^ M2)];
            const float sg = (__popc(b & M1) & 1) ? -1.f : 1.f;
            a0 += sg * mm.x; a1 += sg * mm.y; a2 += sg * mm.z; a3 += sg * mm.w;
        }
        const float s = 0.0625f;
        g_T[t] = make_float4(a0 * s, a1 * s, a2 * s, a3 * s);
    }
}

// ---------------- Kernel 2: batched polynomial evaluation ------------------
#define TPB 128

__global__ __launch_bounds__(TPB, 8)
void vqc_poly_apply(const float* __restrict__ x, float* __restrict__ out, int B) {
    __shared__ float4 sT[81];
    const int t = threadIdx.x;
    if (t < 81) sT[t] = g_T[t];
    __syncthreads();

    const int b = blockIdx.x * TPB + t;
    const float4 xv = (b < B) ? reinterpret_cast<const float4*>(x)[b]
                              : make_float4(0.f, 0.f, 0.f, 0.f);
    float c0, s0, c1, s1, c2, s2, c3, s3;
    __sincosf(xv.x, &s0, &c0);   // full angle (double-angle folded into T)
    __sincosf(xv.y, &s1, &c1);
    __sincosf(xv.z, &s2, &c2);
    __sincosf(xv.w, &s3, &c3);

    // h monomials over (q2,q3), lane-duplicated; h[0]=1 folded into Horner init
    const unsigned long long c2d = pack2(c2, c2), s2d = pack2(s2, s2);
    const unsigned long long c3d = pack2(c3, c3), s3d = pack2(s3, s3);
    unsigned long long h[9];
    h[1] = c3d;            h[2] = s3d;
    h[3] = c2d;            h[6] = s2d;
    h[4] = mul2(c2d, c3d); h[5] = mul2(c2d, s3d);
    h[7] = mul2(s2d, c3d); h[8] = mul2(s2d, s3d);

    // g monomials over (q0,q1), built on the fly
    const unsigned long long c0d = pack2(c0, c0), s0d = pack2(s0, s0);
    const unsigned long long c1d = pack2(c1, c1), s1d = pack2(s1, s1);

    unsigned long long z01 = 0ull, z23 = 0ull;
    const ulonglong2* cT = reinterpret_cast<const ulonglong2*>(sT);

#pragma unroll
    for (int gi = 0; gi < 9; ++gi) {
        // inner = sum_hi T[gi,hi] * h[hi]; init with hi=0 (h=1)
        ulonglong2 c = cT[gi * 9];
        unsigned long long in01 = c.x, in23 = c.y;
#pragma unroll
        for (int hi = 1; hi < 9; ++hi) {
            c = cT[gi * 9 + hi];                 // one LDS.128 -> two b64 pairs
            in01 = fma2(c.x, h[hi], in01);
            in23 = fma2(c.y, h[hi], in23);
        }
        // accumulate with g_gi (g_0 = 1)
        switch (gi) {
            case 0: z01 = in01;                       z23 = in23;                       break;
            case 1: z01 = fma2(c1d, in01, z01);       z23 = fma2(c1d, in23, z23);       break;
            case 2: z01 = fma2(s1d, in01, z01);       z23 = fma2(s1d, in23, z23);       break;
            case 3: z01 = fma2(c0d, in01, z01);       z23 = fma2(c0d, in23, z23);       break;
            case 4: { const unsigned long long g4 = mul2(c0d, c1d);
                      z01 = fma2(g4, in01, z01);      z23 = fma2(g4, in23, z23); }      break;
            case 5: { const unsigned long long g5 = mul2(c0d, s1d);
                      z01 = fma2(g5, in01, z01);      z23 = fma2(g5, in23, z23); }      break;
            case 6: z01 = fma2(s0d, in01, z01);       z23 = fma2(s0d, in23, z23);       break;
            case 7: { const unsigned long long g7 = mul2(s0d, c1d);
                      z01 = fma2(g7, in01, z01);      z23 = fma2(g7, in23, z23); }      break;
            case 8: { const unsigned long long g8 = mul2(s0d, s1d);
                      z01 = fma2(g8, in01, z01);      z23 = fma2(g8, in23, z23); }      break;
        }
    }

    if (b < B) {
        float z0, z1, z2, z3;
        unpack2(z01, z0, z1);
        unpack2(z23, z2, z3);
        reinterpret_cast<float4*>(out)[b] = make_float4(z0, z1, z2, z3);
    }
}

// ---------------------------------------------------------------------------
extern "C" void kernel_launch(void* const* d_in, const int* in_sizes, int n_in,
                              void* d_out, int out_size) {
    int ix = 0, iw = 1;
    if (n_in >= 2 && in_sizes[0] <= in_sizes[1]) { ix = 1; iw = 0; }
    const float* x = (const float*)d_in[ix];
    const float* w = (const float*)d_in[iw];
    float* out = (float*)d_out;
    const int B = in_sizes[ix] / 4;

    vqc_build_T<<<1, 256>>>(w);
    const int grid = (B + TPB - 1) / TPB;
    vqc_poly_apply<<<grid, TPB>>>(x, out, B);
}

// round 9
// speedup vs baseline: 3.8596x; 1.2246x over previous
#include <cuda_runtime.h>
#include <cuda_bf16.h>

// ---------------------------------------------------------------------------
// VQC: 4 qubits, 3 layers, BATCH=524288.
// z_w(x) = exact 81-term polynomial in {1, cos x_q, sin x_q}^{⊗4};
// coefficients T (81 x float4) depend only on weights.
// Kernel 1 (1 block): U -> M_w = Re(U^† S_w U) -> T; triggers PDL early.
// Kernel 2 (EPT=2, TPB=256): per-element Horner over (g=(q0,q1), h=(q2,q3)),
// packed fma.rn.f32x2 lanes = (w0,w1)/(w2,w3); coefficient LDS amortized 2x.
// ---------------------------------------------------------------------------

#define DIM 16

__device__ float4 g_T[81];

// ---------------- packed f32x2 helpers (PTX-only on Blackwell) -------------
__device__ __forceinline__ unsigned long long pack2(float lo, float hi) {
    unsigned long long r;
    asm("mov.b64 %0, {%1, %2};" : "=l"(r) : "f"(lo), "f"(hi));
    return r;
}
__device__ __forceinline__ void unpack2(unsigned long long v, float& lo, float& hi) {
    asm("mov.b64 {%0, %1}, %2;" : "=f"(lo), "=f"(hi) : "l"(v));
}
__device__ __forceinline__ unsigned long long fma2(unsigned long long a,
                                                   unsigned long long b,
                                                   unsigned long long c) {
    unsigned long long d;
    asm("fma.rn.f32x2 %0, %1, %2, %3;" : "=l"(d) : "l"(a), "l"(b), "l"(c));
    return d;
}
__device__ __forceinline__ unsigned long long mul2(unsigned long long a,
                                                   unsigned long long b) {
    unsigned long long d;
    asm("mul.rn.f32x2 %0, %1, %2;" : "=l"(d) : "l"(a), "l"(b));
    return d;
}

// CNOT ring permutation for one layer (gather index).
__device__ __forceinline__ int cnot_q(int idx) {
    int q = idx;
#pragma unroll
    for (int i = 3; i >= 0; --i)
        q = q ^ ((((q >> (3 - i)) & 1)) << (3 - ((i + 1) & 3)));
    return q;
}

// ---------------- Kernel 1: weights -> polynomial coefficients T -----------
__global__ void vqc_build_T(const float* __restrict__ w) {
    __shared__ float2 sState[DIM * 17];
    __shared__ float4 sGate[12];
    __shared__ float4 sM[256];

    const int t = threadIdx.x;

    if (t < 12) {
        float cy, sy, cz, sz;
        __sincosf(0.5f * w[t * 2 + 0], &sy, &cy);
        __sincosf(0.5f * w[t * 2 + 1], &sz, &cz);
        sGate[t] = make_float4(cy, sy, cz, sz);
    }
    {
        const int col = t >> 4, amp = t & 15;
        sState[col * 17 + amp] = make_float2((amp == col) ? 1.0f : 0.0f, 0.0f);
    }
    __syncthreads();

#pragma unroll
    for (int layer = 0; layer < 3; ++layer) {
        {   // CNOT ring stage
            const int col = t >> 4, idx = t & 15;
            const float2 v = sState[col * 17 + cnot_q(idx)];
            __syncthreads();
            sState[col * 17 + idx] = v;
            __syncthreads();
        }
#pragma unroll
        for (int g = 0; g < 4; ++g) {
            if (t < 128) {
                const int bit = 3 - g, mask = 1 << bit;
                const int col = t >> 3, pair = t & 7;
                const int i0 = ((pair >> bit) << (bit + 1)) | (pair & (mask - 1));
                const int i1 = i0 | mask;
                const float4 gp = sGate[layer * 4 + g];
                const float cy = gp.x, sy = gp.y;
                const float2 a0 = sState[col * 17 + i0];
                const float2 a1 = sState[col * 17 + i1];
                float b0r = cy * a0.x - sy * a1.x, b0i = cy * a0.y - sy * a1.y;
                float b1r = sy * a0.x + cy * a1.x, b1i = sy * a0.y + cy * a1.y;
                if (layer != 2) {   // last-layer RZ cancels in U^H S U
                    const float cz = gp.z, sz = gp.w;
                    const float o0r = cz * b0r + sz * b0i, o0i = cz * b0i - sz * b0r;
                    const float o1r = cz * b1r - sz * b1i, o1i = cz * b1i + sz * b1r;
                    b0r = o0r; b0i = o0i; b1r = o1r; b1i = o1i;
                }
                sState[col * 17 + i0] = make_float2(b0r, b0i);
                sState[col * 17 + i1] = make_float2(b1r, b1i);
            }
            __syncthreads();
        }
    }

    // Phase M: M_w[j,j'] = sum_k s_wk (Ur Ur' + Ui Ui')
    {
        const int j = t >> 4, jp = t & 15;
        float m0 = 0.f, m1 = 0.f, m2 = 0.f, m3 = 0.f;
#pragma unroll
        for (int k = 0; k < DIM; ++k) {
            const float2 a = sState[j * 17 + k];
            const float2 b = sState[jp * 17 + k];
            const float pr = a.x * b.x + a.y * b.y;
            if (k & 8) m0 -= pr; else m0 += pr;
            if (k & 4) m1 -= pr; else m1 += pr;
            if (k & 2) m2 -= pr; else m2 += pr;
            if (k & 1) m3 -= pr; else m3 += pr;
        }
        sM[j * 16 + jp] = make_float4(m0, m1, m2, m3);
    }
    __syncthreads();

    // Phase T -> global, then early PDL trigger
    if (t < 81) {
        const int i0 = t / 27, i1 = (t / 9) % 3, i2 = (t / 3) % 3, i3 = t % 3;
        const int M1 = ((i0 == 1) << 3) | ((i1 == 1) << 2) | ((i2 == 1) << 1) | (i3 == 1);
        const int M2 = ((i0 == 2) << 3) | ((i1 == 2) << 2) | ((i2 == 2) << 1) | (i3 == 2);
        float a0 = 0.f, a1 = 0.f, a2 = 0.f, a3 = 0.f;
#pragma unroll
        for (int b = 0; b < 16; ++b) {
            const float4 mm = sM[b * 16 + (b ^ M2)];
            const float sg = (__popc(b & M1) & 1) ? -1.f : 1.f;
            a0 += sg * mm.x; a1 += sg * mm.y; a2 += sg * mm.z; a3 += sg * mm.w;
        }
        const float s = 0.0625f;
        g_T[t] = make_float4(a0 * s, a1 * s, a2 * s, a3 * s);
        __threadfence();
    }
    __syncthreads();
    cudaTriggerProgrammaticLaunchCompletion();
}

// ---------------- Kernel 2: batched polynomial evaluation (EPT=2) ----------
#define TPB 256
#define EPT 2
#define TILE (TPB * EPT)

__global__ __launch_bounds__(TPB, 3)
void vqc_poly_apply(const float* __restrict__ x, float* __restrict__ out, int B) {
    __shared__ float4 sT[81];
    const int t = threadIdx.x;
    const int base = blockIdx.x * TILE + t;

    // ---- builder-independent preamble (overlaps PDL wait) ----
    bool valid[EPT];
    unsigned long long h[EPT][9];                     // h[.][1..8]
    unsigned long long c0d[EPT], s0d[EPT], c1d[EPT], s1d[EPT];
#pragma unroll
    for (int e = 0; e < EPT; ++e) {
        const int b = base + e * TPB;
        valid[e] = (b < B);
        const float4 xv = valid[e] ? reinterpret_cast<const float4*>(x)[b]
                                   : make_float4(0.f, 0.f, 0.f, 0.f);
        float c0, s0, c1, s1, c2, s2, c3, s3;
        __sincosf(xv.x, &s0, &c0);   // full angle (double-angle folded into T)
        __sincosf(xv.y, &s1, &c1);
        __sincosf(xv.z, &s2, &c2);
        __sincosf(xv.w, &s3, &c3);
        c0d[e] = pack2(c0, c0); s0d[e] = pack2(s0, s0);
        c1d[e] = pack2(c1, c1); s1d[e] = pack2(s1, s1);
        const unsigned long long c2d = pack2(c2, c2), s2d = pack2(s2, s2);
        const unsigned long long c3d = pack2(c3, c3), s3d = pack2(s3, s3);
        h[e][1] = c3d;            h[e][2] = s3d;
        h[e][3] = c2d;            h[e][6] = s2d;
        h[e][4] = mul2(c2d, c3d); h[e][5] = mul2(c2d, s3d);
        h[e][7] = mul2(s2d, c3d); h[e][8] = mul2(s2d, s3d);
    }

    // ---- wait for builder, stage T into smem ----
    cudaGridDependencySynchronize();
    if (t < 81) sT[t] = g_T[t];
    __syncthreads();

    unsigned long long z01[EPT], z23[EPT];
    const ulonglong2* cT = reinterpret_cast<const ulonglong2*>(sT);

#pragma unroll
    for (int gi = 0; gi < 9; ++gi) {
        // inner[e] = sum_hi T[gi,hi] * h[e][hi]  (hi=0 term: h=1)
        ulonglong2 c = cT[gi * 9];
        unsigned long long in01[EPT], in23[EPT];
#pragma unroll
        for (int e = 0; e < EPT; ++e) { in01[e] = c.x; in23[e] = c.y; }
#pragma unroll
        for (int hi = 1; hi < 9; ++hi) {
            c = cT[gi * 9 + hi];              // one LDS.128 serves both elements
#pragma unroll
            for (int e = 0; e < EPT; ++e) {
                in01[e] = fma2(c.x, h[e][hi], in01[e]);
                in23[e] = fma2(c.y, h[e][hi], in23[e]);
            }
        }
        // accumulate with g_gi (g_0 = 1); products built on the fly
#pragma unroll
        for (int e = 0; e < EPT; ++e) {
            switch (gi) {
                case 0: z01[e] = in01[e];                    z23[e] = in23[e];                    break;
                case 1: z01[e] = fma2(c1d[e], in01[e], z01[e]); z23[e] = fma2(c1d[e], in23[e], z23[e]); break;
                case 2: z01[e] = fma2(s1d[e], in01[e], z01[e]); z23[e] = fma2(s1d[e], in23[e], z23[e]); break;
                case 3: z01[e] = fma2(c0d[e], in01[e], z01[e]); z23[e] = fma2(c0d[e], in23[e], z23[e]); break;
                case 4: { const unsigned long long g = mul2(c0d[e], c1d[e]);
                          z01[e] = fma2(g, in01[e], z01[e]);  z23[e] = fma2(g, in23[e], z23[e]); } break;
                case 5: { const unsigned long long g = mul2(c0d[e], s1d[e]);
                          z01[e] = fma2(g, in01[e], z01[e]);  z23[e] = fma2(g, in23[e], z23[e]); } break;
                case 6: z01[e] = fma2(s0d[e], in01[e], z01[e]); z23[e] = fma2(s0d[e], in23[e], z23[e]); break;
                case 7: { const unsigned long long g = mul2(s0d[e], c1d[e]);
                          z01[e] = fma2(g, in01[e], z01[e]);  z23[e] = fma2(g, in23[e], z23[e]); } break;
                case 8: { const unsigned long long g = mul2(s0d[e], s1d[e]);
                          z01[e] = fma2(g, in01[e], z01[e]);  z23[e] = fma2(g, in23[e], z23[e]); } break;
            }
        }
    }

#pragma unroll
    for (int e = 0; e < EPT; ++e) {
        if (!valid[e]) continue;
        float z0, z1, z2, z3;
        unpack2(z01[e], z0, z1);
        unpack2(z23[e], z2, z3);
        reinterpret_cast<float4*>(out)[base + e * TPB] = make_float4(z0, z1, z2, z3);
    }
}

// ---------------------------------------------------------------------------
extern "C" void kernel_launch(void* const* d_in, const int* in_sizes, int n_in,
                              void* d_out, int out_size) {
    int ix = 0, iw = 1;
    if (n_in >= 2 && in_sizes[0] <= in_sizes[1]) { ix = 1; iw = 0; }
    const float* x = (const float*)d_in[ix];
    const float* w = (const float*)d_in[iw];
    float* out = (float*)d_out;
    const int B = in_sizes[ix] / 4;

    vqc_build_T<<<1, 256>>>(w);

    const int grid = (B + TILE - 1) / TILE;
    cudaLaunchConfig_t cfg = {};
    cfg.gridDim = dim3(grid, 1, 1);
    cfg.blockDim = dim3(TPB, 1, 1);
    cudaLaunchAttribute attr[1];
    attr[0].id = cudaLaunchAttributeProgrammaticStreamSerialization;
    attr[0].val.programmaticStreamSerializationAllowed = 1;
    cfg.attrs = attr;
    cfg.numAttrs = 1;
    cudaLaunchKernelEx(&cfg, vqc_poly_apply, x, out, B);
}

// round 10
// speedup vs baseline: 4.1462x; 1.0742x over previous
#include <cuda_runtime.h>
#include <cuda_bf16.h>

// ---------------------------------------------------------------------------
// VQC: 4 qubits, 3 layers, BATCH=524288.
// z_w(x) = exact 81-term polynomial in {1, cos x_q, sin x_q}^{⊗4};
// coefficients T (81 x float4) depend only on weights.
// Kernel 1 (1 block): U -> M_w = Re(U^† S_w U) -> T; PDL trigger.
// Kernel 2 (EPT=2, TPB=128, 7 CTAs/SM): fully nested contraction
//   z = Σ_gi g_gi Σ_i2 v2[i2] Σ_i3 T[gi,i2,i3] v3[i3]
// packed fma.rn.f32x2 lanes = (w0,w1)/(w2,w3); 3-coeff chunks keep live regs ~70.
// ---------------------------------------------------------------------------

#define DIM 16

__device__ float4 g_T[81];

// ---------------- packed f32x2 helpers (PTX-only on Blackwell) -------------
__device__ __forceinline__ unsigned long long pack2(float lo, float hi) {
    unsigned long long r;
    asm("mov.b64 %0, {%1, %2};" : "=l"(r) : "f"(lo), "f"(hi));
    return r;
}
__device__ __forceinline__ void unpack2(unsigned long long v, float& lo, float& hi) {
    asm("mov.b64 {%0, %1}, %2;" : "=f"(lo), "=f"(hi) : "l"(v));
}
__device__ __forceinline__ unsigned long long fma2(unsigned long long a,
                                                   unsigned long long b,
                                                   unsigned long long c) {
    unsigned long long d;
    asm("fma.rn.f32x2 %0, %1, %2, %3;" : "=l"(d) : "l"(a), "l"(b), "l"(c));
    return d;
}
__device__ __forceinline__ unsigned long long mul2(unsigned long long a,
                                                   unsigned long long b) {
    unsigned long long d;
    asm("mul.rn.f32x2 %0, %1, %2;" : "=l"(d) : "l"(a), "l"(b));
    return d;
}

// CNOT ring permutation for one layer (gather index).
__device__ __forceinline__ int cnot_q(int idx) {
    int q = idx;
#pragma unroll
    for (int i = 3; i >= 0; --i)
        q = q ^ ((((q >> (3 - i)) & 1)) << (3 - ((i + 1) & 3)));
    return q;
}

// ---------------- Kernel 1: weights -> polynomial coefficients T -----------
__global__ void vqc_build_T(const float* __restrict__ w) {
    __shared__ float2 sState[DIM * 17];
    __shared__ float4 sGate[12];
    __shared__ float4 sM[256];

    const int t = threadIdx.x;

    if (t < 12) {
        float cy, sy, cz, sz;
        __sincosf(0.5f * w[t * 2 + 0], &sy, &cy);
        __sincosf(0.5f * w[t * 2 + 1], &sz, &cz);
        sGate[t] = make_float4(cy, sy, cz, sz);
    }
    {
        const int col = t >> 4, amp = t & 15;
        sState[col * 17 + amp] = make_float2((amp == col) ? 1.0f : 0.0f, 0.0f);
    }
    __syncthreads();

#pragma unroll
    for (int layer = 0; layer < 3; ++layer) {
        {   // CNOT ring stage
            const int col = t >> 4, idx = t & 15;
            const float2 v = sState[col * 17 + cnot_q(idx)];
            __syncthreads();
            sState[col * 17 + idx] = v;
            __syncthreads();
        }
#pragma unroll
        for (int g = 0; g < 4; ++g) {
            if (t < 128) {
                const int bit = 3 - g, mask = 1 << bit;
                const int col = t >> 3, pair = t & 7;
                const int i0 = ((pair >> bit) << (bit + 1)) | (pair & (mask - 1));
                const int i1 = i0 | mask;
                const float4 gp = sGate[layer * 4 + g];
                const float cy = gp.x, sy = gp.y;
                const float2 a0 = sState[col * 17 + i0];
                const float2 a1 = sState[col * 17 + i1];
                float b0r = cy * a0.x - sy * a1.x, b0i = cy * a0.y - sy * a1.y;
                float b1r = sy * a0.x + cy * a1.x, b1i = sy * a0.y + cy * a1.y;
                if (layer != 2) {   // last-layer RZ cancels in U^H S U
                    const float cz = gp.z, sz = gp.w;
                    const float o0r = cz * b0r + sz * b0i, o0i = cz * b0i - sz * b0r;
                    const float o1r = cz * b1r - sz * b1i, o1i = cz * b1i + sz * b1r;
                    b0r = o0r; b0i = o0i; b1r = o1r; b1i = o1i;
                }
                sState[col * 17 + i0] = make_float2(b0r, b0i);
                sState[col * 17 + i1] = make_float2(b1r, b1i);
            }
            __syncthreads();
        }
    }

    // Phase M: M_w[j,j'] = sum_k s_wk (Ur Ur' + Ui Ui')
    {
        const int j = t >> 4, jp = t & 15;
        float m0 = 0.f, m1 = 0.f, m2 = 0.f, m3 = 0.f;
#pragma unroll
        for (int k = 0; k < DIM; ++k) {
            const float2 a = sState[j * 17 + k];
            const float2 b = sState[jp * 17 + k];
            const float pr = a.x * b.x + a.y * b.y;
            if (k & 8) m0 -= pr; else m0 += pr;
            if (k & 4) m1 -= pr; else m1 += pr;
            if (k & 2) m2 -= pr; else m2 += pr;
            if (k & 1) m3 -= pr; else m3 += pr;
        }
        sM[j * 16 + jp] = make_float4(m0, m1, m2, m3);
    }
    __syncthreads();

    // Phase T -> global, then PDL trigger
    if (t < 81) {
        const int i0 = t / 27, i1 = (t / 9) % 3, i2 = (t / 3) % 3, i3 = t % 3;
        const int M1 = ((i0 == 1) << 3) | ((i1 == 1) << 2) | ((i2 == 1) << 1) | (i3 == 1);
        const int M2 = ((i0 == 2) << 3) | ((i1 == 2) << 2) | ((i2 == 2) << 1) | (i3 == 2);
        float a0 = 0.f, a1 = 0.f, a2 = 0.f, a3 = 0.f;
#pragma unroll
        for (int b = 0; b < 16; ++b) {
            const float4 mm = sM[b * 16 + (b ^ M2)];
            const float sg = (__popc(b & M1) & 1) ? -1.f : 1.f;
            a0 += sg * mm.x; a1 += sg * mm.y; a2 += sg * mm.z; a3 += sg * mm.w;
        }
        const float s = 0.0625f;
        g_T[t] = make_float4(a0 * s, a1 * s, a2 * s, a3 * s);
        __threadfence();
    }
    __syncthreads();
    cudaTriggerProgrammaticLaunchCompletion();
}

// ---------------- Kernel 2: batched polynomial evaluation ------------------
#define TPB 128
#define EPT 2
#define TILE (TPB * EPT)

__global__ __launch_bounds__(TPB, 7)
void vqc_poly_apply(const float* __restrict__ x, float* __restrict__ out, int B) {
    __shared__ float4 sT[81];
    const int t = threadIdx.x;
    const int base = blockIdx.x * TILE + t;

    // ---- builder-independent preamble (overlaps PDL wait) ----
    bool valid[EPT];
    unsigned long long c0d[EPT], s0d[EPT], c1d[EPT], s1d[EPT];
    unsigned long long c2d[EPT], s2d[EPT], c3d[EPT], s3d[EPT];
#pragma unroll
    for (int e = 0; e < EPT; ++e) {
        const int b = base + e * TPB;
        valid[e] = (b < B);
        const float4 xv = valid[e] ? reinterpret_cast<const float4*>(x)[b]
                                   : make_float4(0.f, 0.f, 0.f, 0.f);
        float c0, s0, c1, s1, c2, s2, c3, s3;
        __sincosf(xv.x, &s0, &c0);   // full angle (double-angle folded into T)
        __sincosf(xv.y, &s1, &c1);
        __sincosf(xv.z, &s2, &c2);
        __sincosf(xv.w, &s3, &c3);
        c0d[e] = pack2(c0, c0); s0d[e] = pack2(s0, s0);
        c1d[e] = pack2(c1, c1); s1d[e] = pack2(s1, s1);
        c2d[e] = pack2(c2, c2); s2d[e] = pack2(s2, s2);
        c3d[e] = pack2(c3, c3); s3d[e] = pack2(s3, s3);
    }

    // ---- wait for builder, stage T into smem ----
    cudaGridDependencySynchronize();
    if (t < 81) sT[t] = g_T[t];
    __syncthreads();

    unsigned long long z01[EPT], z23[EPT];
    const ulonglong2* cT = reinterpret_cast<const ulonglong2*>(sT);

#pragma unroll
    for (int gi = 0; gi < 9; ++gi) {
        unsigned long long in01[EPT], in23[EPT];
        // nested (i2,(i3)) contraction: 3 coeff-pairs live at a time
#pragma unroll
        for (int i2 = 0; i2 < 3; ++i2) {
            const ulonglong2 ca = cT[gi * 9 + i2 * 3 + 0];
            const ulonglong2 cb = cT[gi * 9 + i2 * 3 + 1];
            const ulonglong2 cc = cT[gi * 9 + i2 * 3 + 2];
#pragma unroll
            for (int e = 0; e < EPT; ++e) {
                const unsigned long long u01 =
                    fma2(cc.x, s3d[e], fma2(cb.x, c3d[e], ca.x));
                const unsigned long long u23 =
                    fma2(cc.y, s3d[e], fma2(cb.y, c3d[e], ca.y));
                if (i2 == 0)      { in01[e] = u01;                       in23[e] = u23; }
                else if (i2 == 1) { in01[e] = fma2(u01, c2d[e], in01[e]); in23[e] = fma2(u23, c2d[e], in23[e]); }
                else              { in01[e] = fma2(u01, s2d[e], in01[e]); in23[e] = fma2(u23, s2d[e], in23[e]); }
            }
        }
        // accumulate with g_gi over (q0,q1); g_0 = 1
#pragma unroll
        for (int e = 0; e < EPT; ++e) {
            switch (gi) {
                case 0: z01[e] = in01[e];                       z23[e] = in23[e];                       break;
                case 1: z01[e] = fma2(c1d[e], in01[e], z01[e]); z23[e] = fma2(c1d[e], in23[e], z23[e]); break;
                case 2: z01[e] = fma2(s1d[e], in01[e], z01[e]); z23[e] = fma2(s1d[e], in23[e], z23[e]); break;
                case 3: z01[e] = fma2(c0d[e], in01[e], z01[e]); z23[e] = fma2(c0d[e], in23[e], z23[e]); break;
                case 4: { const unsigned long long g = mul2(c0d[e], c1d[e]);
                          z01[e] = fma2(g, in01[e], z01[e]);    z23[e] = fma2(g, in23[e], z23[e]); }    break;
                case 5: { const unsigned long long g = mul2(c0d[e], s1d[e]);
                          z01[e] = fma2(g, in01[e], z01[e]);    z23[e] = fma2(g, in23[e], z23[e]); }    break;
                case 6: z01[e] = fma2(s0d[e], in01[e], z01[e]); z23[e] = fma2(s0d[e], in23[e], z23[e]); break;
                case 7: { const unsigned long long g = mul2(s0d[e], c1d[e]);
                          z01[e] = fma2(g, in01[e], z01[e]);    z23[e] = fma2(g, in23[e], z23[e]); }    break;
                case 8: { const unsigned long long g = mul2(s0d[e], s1d[e]);
                          z01[e] = fma2(g, in01[e], z01[e]);    z23[e] = fma2(g, in23[e], z23[e]); }    break;
            }
        }
    }

#pragma unroll
    for (int e = 0; e < EPT; ++e) {
        if (!valid[e]) continue;
        float z0, z1, z2, z3;
        unpack2(z01[e], z0, z1);
        unpack2(z23[e], z2, z3);
        reinterpret_cast<float4*>(out)[base + e * TPB] = make_float4(z0, z1, z2, z3);
    }
}

// ---------------------------------------------------------------------------
extern "C" void kernel_launch(void* const* d_in, const int* in_sizes, int n_in,
                              void* d_out, int out_size) {
    int ix = 0, iw = 1;
    if (n_in >= 2 && in_sizes[0] <= in_sizes[1]) { ix = 1; iw = 0; }
    const float* x = (const float*)d_in[ix];
    const float* w = (const float*)d_in[iw];
    float* out = (float*)d_out;
    const int B = in_sizes[ix] / 4;

    vqc_build_T<<<1, 256>>>(w);

    const int grid = (B + TILE - 1) / TILE;
    cudaLaunchConfig_t cfg = {};
    cfg.gridDim = dim3(grid, 1, 1);
    cfg.blockDim = dim3(TPB, 1, 1);
    cudaLaunchAttribute attr[1];
    attr[0].id = cudaLaunchAttributeProgrammaticStreamSerialization;
    attr[0].val.programmaticStreamSerializationAllowed = 1;
    cfg.attrs = attr;
    cfg.numAttrs = 1;
    cudaLaunchKernelEx(&cfg, vqc_poly_apply, x, out, B);
}